// round 4
// baseline (speedup 1.0000x reference)
#include <cuda_runtime.h>

#define NJ   17
#define NP   14
#define NB   256
#define NCH  59              // 17 + 3*14
#define NBLK (NCH * NB)      // 15104 uniform blocks

__constant__ int c_par[NP] = {0,1,2,0,4,5,0,8,14,15,8,11,12,8};
__constant__ int c_chi[NP] = {1,2,3,4,5,6,8,14,15,16,11,12,13,10};

// Per-block partials, indexed [b*NCH + ch]. Every slot written every launch.
__device__ float        g_part[NBLK];
__device__ unsigned int g_count;   // zero at load; last block resets each call

// max over integer grid i in [0,63] of exp(-(i-x)^2/4): nearest grid point.
__device__ __forceinline__ float gmax1d(float x) {
    float i = fminf(fmaxf(rintf(x), 0.f), 63.f);
    float d = i - x;
    return __expf(-d * d * 0.25f);
}

__device__ __forceinline__ float blockReduce256(float v, float* red, int tid) {
    #pragma unroll
    for (int o = 16; o > 0; o >>= 1) v += __shfl_down_sync(0xffffffffu, v, o);
    if ((tid & 31) == 0) red[tid >> 5] = v;
    __syncthreads();
    v = (tid < 8) ? red[tid] : 0.f;
    if (tid < 32) {
        #pragma unroll
        for (int o = 4; o > 0; o >>= 1) v += __shfl_down_sync(0xffffffffu, v, o);
    }
    return v;   // valid on tid 0
}

__global__ void __launch_bounds__(256, 8)
k_fused(const float* __restrict__ mo,
        const float* __restrict__ joints,
        const float* __restrict__ j2d,
        const float* __restrict__ pred,
        float* __restrict__ out) {
    __shared__ __align__(16) float exA[64], eyA[64], exB[64], eyB[64];
    __shared__ float red[8];
    __shared__ int   s_last;

    const int ch  = blockIdx.x;
    const int b   = blockIdx.y;
    const int tid = threadIdx.x;

    // ---- decode channel -> (jointA, jointB, weights wa, wb) ----
    int jA, jB;
    float wa, wb;
    if (ch < NJ) {
        jA = ch; jB = ch; wa = 1.f; wb = 0.f;
    } else {
        int q  = ch - NJ;
        int pr = q / 3;
        int c  = q - 3 * pr;
        jA = c_par[pr]; jB = c_chi[pr];
        float dz = joints[(b * NJ + jA) * 3 + 2] - joints[(b * NJ + jB) * 3 + 2];
        int r = (dz > 0.1f) ? 1 : ((fabsf(dz) < 0.1f) ? 0 : -1);
        // T_GT channels: c0 = (r==-1)?hc:0 ; c1 = hp + (r==0)?hc:0 ; c2 = (r==1)?hc:0
        wa = (c == 1) ? 1.f : 0.f;
        wb = ((c == 0 && r == -1) || (c == 1 && r == 0) || (c == 2 && r == 1)) ? 1.f : 0.f;
    }

    // ---- build tables: weights + normalization folded into ex tables ----
    const float xA = j2d[(b * NJ + jA) * 2 + 0] * 64.f;
    const float yA = j2d[(b * NJ + jA) * 2 + 1] * 64.f;
    const float xB = j2d[(b * NJ + jB) * 2 + 0] * 64.f;
    const float yB = j2d[(b * NJ + jB) * 2 + 1] * 64.f;
    const float sA = wa / (gmax1d(xA) * gmax1d(yA));
    const float sB = wb / (gmax1d(xB) * gmax1d(yB));
    {
        int g = tid & 63;
        float fg = (float)g;
        if (tid < 64)       { float d = fg - xA; exA[g] = expf(-d * d * 0.25f) * sA; }
        else if (tid < 128) { float d = fg - yA; eyA[g] = expf(-d * d * 0.25f); }
        else if (tid < 192) { float d = fg - xB; exB[g] = expf(-d * d * 0.25f) * sB; }
        else                { float d = fg - yB; eyB[g] = expf(-d * d * 0.25f); }
    }
    __syncthreads();

    // ---- stream 4096 floats of this channel ----
    const float4* p = (const float4*)(mo + (((size_t)b * NCH + ch) << 12));
    float acc = 0.f;
    #pragma unroll
    for (int it = 0; it < 4; it++) {
        int e4 = tid + it * 256;
        float4 m = __ldcs(&p[e4]);
        int i  = e4 >> 4;       // row    0..63
        int k4 = e4 & 15;       // float4 column index
        float aA = exA[i];
        float aB = exB[i];
        float4 vA = ((const float4*)eyA)[k4];
        float4 vB = ((const float4*)eyB)[k4];
        float d0 = m.x - (aA * vA.x + aB * vB.x);
        float d1 = m.y - (aA * vA.y + aB * vB.y);
        float d2 = m.z - (aA * vA.z + aB * vB.z);
        float d3 = m.w - (aA * vA.w + aB * vB.w);
        acc += d0 * d0 + d1 * d1 + d2 * d2 + d3 * d3;
    }
    float partial = blockReduce256(acc, red, tid);

    // ---- publish, detect last block ----
    if (tid == 0) {
        g_part[b * NCH + ch] = partial;
        __threadfence();
        unsigned int prev = atomicAdd(&g_count, 1u);
        s_last = (prev == (unsigned)(NBLK - 1)) ? 1 : 0;
    }
    __syncthreads();
    if (!s_last) return;

    // ---- last block: combine. thread tid = batch tid ----
    const float* pp = g_part + tid * NCH;
    float l2d = 0.f;
    #pragma unroll
    for (int c = 0; c < NJ; c++) l2d += __ldcg(&pp[c]);
    float hem = 0.f;
    #pragma unroll
    for (int pr = 0; pr < NP; pr++) {
        float s0 = __ldcg(&pp[NJ + 3 * pr + 0]);
        float s1 = __ldcg(&pp[NJ + 3 * pr + 1]);
        float s2 = __ldcg(&pp[NJ + 3 * pr + 2]);
        float t = sqrtf(s0) + sqrtf(s1) + sqrtf(s2);
        hem += t * t;
    }

    // l3d: 51 abs-diffs for batch tid
    float l = 0.f;
    const float* jb = joints + tid * NJ * 3;
    const float* pb = pred   + tid * NJ * 3;
    #pragma unroll
    for (int i = 0; i < NJ * 3; i++) l += fabsf(jb[i] - pb[i]);

    float v = l + 0.005f * (l2d + hem);
    __syncthreads();   // red[] reuse
    float tot = blockReduce256(v, red, tid);
    if (tid == 0) {
        out[0] = tot * (1.f / 256.f);
        g_count = 0;   // reset for next graph replay
    }
}

extern "C" void kernel_launch(void* const* d_in, const int* in_sizes, int n_in,
                              void* d_out, int out_size) {
    const float* pred   = (const float*)d_in[0];
    const float* joints = (const float*)d_in[1];
    const float* mo     = (const float*)d_in[2];
    const float* j2d    = (const float*)d_in[3];
    float* out = (float*)d_out;

    k_fused<<<dim3(NCH, NB), 256>>>(mo, joints, j2d, pred, out);
}

// round 5
// speedup vs baseline: 1.0115x; 1.0115x over previous
#include <cuda_runtime.h>

#define NJ   17
#define NP   14
#define NB   256
#define NCH  59                 // 17 + 3*14
#define NGRP 20                 // 14 HEM pair-blocks + 6 L2D triple-blocks
#define NBLK (NGRP * NB)        // 5120 blocks total

__constant__ int c_par[NP] = {0,1,2,0,4,5,0,8,14,15,8,11,12,8};
__constant__ int c_chi[NP] = {1,2,3,4,5,6,8,14,15,16,11,12,13,10};

// Per-channel partial sums, indexed [b*NCH + ch]. All valid slots written every launch.
__device__ float        g_part[NB * NCH];
__device__ unsigned int g_count;   // zero at module load; last block resets each call

// max over integer grid i in [0,63] of exp(-(i-x)^2/4): nearest grid point.
__device__ __forceinline__ float gmax1d(float x) {
    float i = fminf(fmaxf(rintf(x), 0.f), 63.f);
    float d = i - x;
    return __expf(-d * d * 0.25f);
}

__device__ __forceinline__ float blockReduce256(float v, float* red, int tid) {
    #pragma unroll
    for (int o = 16; o > 0; o >>= 1) v += __shfl_down_sync(0xffffffffu, v, o);
    if ((tid & 31) == 0) red[tid >> 5] = v;
    __syncthreads();
    v = (tid < 8) ? red[tid] : 0.f;
    if (tid < 32) {
        #pragma unroll
        for (int o = 4; o > 0; o >>= 1) v += __shfl_down_sync(0xffffffffu, v, o);
    }
    return v;   // valid on tid 0
}

__global__ void __launch_bounds__(256, 8)
k_fused(const float* __restrict__ mo,
        const float* __restrict__ joints,
        const float* __restrict__ j2d,
        const float* __restrict__ pred,
        float* __restrict__ out) {
    // 6 tables of 64 floats: [0]=exA [1]=eyA [2]=exB [3]=eyB [4]=exC [5]=eyC
    __shared__ __align__(16) float tab[6][64];
    __shared__ float red[8];
    __shared__ int   s_last;

    const int bx  = blockIdx.x;          // 0..13 HEM pair, 14..19 L2D triple
    const int b   = blockIdx.y;
    const int tid = threadIdx.x;
    const bool isHem = (bx < NP);

    int   ch0;                  // first canonical channel of this block
    int   nch = 3;              // channels handled (2 for last L2D group)
    float w0 = 0.f, w1 = 0.f, w2 = 0.f;   // HEM: weight of hc in each channel

    if (isHem) {
        const int pr = bx;
        ch0 = NJ + 3 * pr;
        const int pj = c_par[pr], cj = c_chi[pr];
        const float xp = j2d[(b * NJ + pj) * 2 + 0] * 64.f;
        const float yp = j2d[(b * NJ + pj) * 2 + 1] * 64.f;
        const float xc = j2d[(b * NJ + cj) * 2 + 0] * 64.f;
        const float yc = j2d[(b * NJ + cj) * 2 + 1] * 64.f;
        const float invp = 1.f / (gmax1d(xp) * gmax1d(yp));
        const float invc = 1.f / (gmax1d(xc) * gmax1d(yc));
        const float dz = joints[(b * NJ + pj) * 3 + 2] - joints[(b * NJ + cj) * 3 + 2];
        const int r = (dz > 0.1f) ? 1 : ((fabsf(dz) < 0.1f) ? 0 : -1);
        w0 = (r == -1) ? 1.f : 0.f;
        w1 = (r ==  0) ? 1.f : 0.f;
        w2 = (r ==  1) ? 1.f : 0.f;
        // tables: exA=parent-x (scaled), eyA=parent-y, exB=child-x (scaled), eyB=child-y
        const int t = tid >> 6, g = tid & 63;
        const float fg = (float)g;
        if      (t == 0) { float d = fg - xp; tab[0][g] = expf(-d * d * 0.25f) * invp; }
        else if (t == 1) { float d = fg - yp; tab[1][g] = expf(-d * d * 0.25f); }
        else if (t == 2) { float d = fg - xc; tab[2][g] = expf(-d * d * 0.25f) * invc; }
        else             { float d = fg - yc; tab[3][g] = expf(-d * d * 0.25f); }
    } else {
        const int grp = bx - NP;           // 0..5
        ch0 = 3 * grp;
        if (grp == 5) nch = 2;             // joints 15,16 only
        // tables for up to 3 joints: (ex,ey) pairs in tab[2c],tab[2c+1]
        const int t = tid >> 6, g = tid & 63;
        const float fg = (float)g;
        // round 1: tables 0..3 (joints ch0, ch0+1)
        {
            const int c = t >> 1;                 // 0 or 1
            const int j = ch0 + c;
            const float x = j2d[(b * NJ + j) * 2 + 0] * 64.f;
            const float y = j2d[(b * NJ + j) * 2 + 1] * 64.f;
            if ((t & 1) == 0) {
                float inv = 1.f / (gmax1d(x) * gmax1d(y));
                float d = fg - x; tab[2 * c][g] = expf(-d * d * 0.25f) * inv;
            } else {
                float d = fg - y; tab[2 * c + 1][g] = expf(-d * d * 0.25f);
            }
        }
        // round 2: tables 4,5 (joint ch0+2) — only when it exists
        if (nch == 3 && tid < 128) {
            const int j = ch0 + 2;
            const float x = j2d[(b * NJ + j) * 2 + 0] * 64.f;
            const float y = j2d[(b * NJ + j) * 2 + 1] * 64.f;
            if (t == 0) {
                float inv = 1.f / (gmax1d(x) * gmax1d(y));
                float d = fg - x; tab[4][g] = expf(-d * d * 0.25f) * inv;
            } else {
                float d = fg - y; tab[5][g] = expf(-d * d * 0.25f);
            }
        }
    }
    __syncthreads();

    // ---- stream 3 channels x 16KB ----
    const float4* p = (const float4*)(mo + (((size_t)b * NCH + ch0) << 12));
    float a0 = 0.f, a1 = 0.f, a2 = 0.f;
    const float4* eyA4 = (const float4*)tab[1];
    const float4* eyB4 = (const float4*)tab[3];
    const float4* eyC4 = (const float4*)tab[5];

    if (isHem) {
        const float nw0 = -w0, nw1 = -w1, nw2 = -w2;
        #pragma unroll
        for (int it = 0; it < 4; it++) {
            const int e4 = tid + it * 256;
            float4 m0 = __ldcs(&p[e4]);
            float4 m1 = __ldcs(&p[e4 + 1024]);
            float4 m2 = __ldcs(&p[e4 + 2048]);
            const int i  = e4 >> 4;
            const int k4 = e4 & 15;
            const float aP = tab[0][i];
            const float aB = tab[2][i];
            const float4 vP = eyA4[k4];
            const float4 vB = eyB4[k4];
            #pragma unroll
            for (int n = 0; n < 4; n++) {
                const float mp = (&m0.x)[n], mm = (&m1.x)[n], mc = (&m2.x)[n];
                const float vp = (&vP.x)[n], vb = (&vB.x)[n];
                const float hp = aP * vp;
                const float hc = aB * vb;
                float d0 = fmaf(nw0, hc, mp);                 // m0 - w0*hc
                float d1 = fmaf(nw1, hc, mm - hp);            // m1 - hp - w1*hc
                float d2 = fmaf(nw2, hc, mc);                 // m2 - w2*hc
                a0 = fmaf(d0, d0, a0);
                a1 = fmaf(d1, d1, a1);
                a2 = fmaf(d2, d2, a2);
            }
        }
    } else {
        const bool n3 = (nch == 3);
        #pragma unroll
        for (int it = 0; it < 4; it++) {
            const int e4 = tid + it * 256;
            float4 m0 = __ldcs(&p[e4]);
            float4 m1 = __ldcs(&p[e4 + 1024]);
            float4 m2;
            if (n3) m2 = __ldcs(&p[e4 + 2048]);
            const int i  = e4 >> 4;
            const int k4 = e4 & 15;
            const float s0 = tab[0][i];
            const float s1 = tab[2][i];
            const float s2 = n3 ? tab[4][i] : 0.f;
            const float4 v0 = eyA4[k4];
            const float4 v1 = eyB4[k4];
            const float4 v2 = n3 ? eyC4[k4] : make_float4(0.f, 0.f, 0.f, 0.f);
            #pragma unroll
            for (int n = 0; n < 4; n++) {
                float d0 = fmaf(-s0, (&v0.x)[n], (&m0.x)[n]);
                float d1 = fmaf(-s1, (&v1.x)[n], (&m1.x)[n]);
                a0 = fmaf(d0, d0, a0);
                a1 = fmaf(d1, d1, a1);
                if (n3) {
                    float d2 = fmaf(-s2, (&v2.x)[n], (&m2.x)[n]);
                    a2 = fmaf(d2, d2, a2);
                }
            }
        }
    }

    // ---- per-channel block reductions ----
    float S0 = blockReduce256(a0, red, tid);
    __syncthreads();
    float S1 = blockReduce256(a1, red, tid);
    __syncthreads();
    float S2 = blockReduce256(a2, red, tid);

    // ---- publish, detect last block ----
    if (tid == 0) {
        float* dst = &g_part[b * NCH + ch0];
        dst[0] = S0;
        dst[1] = S1;
        if (nch == 3) dst[2] = S2;
        __threadfence();
        unsigned int prev = atomicAdd(&g_count, 1u);
        s_last = (prev == (unsigned)(NBLK - 1)) ? 1 : 0;
    }
    __syncthreads();
    if (!s_last) return;

    // ---- last block: combine. thread tid = batch tid ----
    const float* pp = g_part + tid * NCH;
    float l2d = 0.f;
    #pragma unroll
    for (int c = 0; c < NJ; c++) l2d += __ldcg(&pp[c]);
    float hem = 0.f;
    #pragma unroll
    for (int pr = 0; pr < NP; pr++) {
        float s0 = __ldcg(&pp[NJ + 3 * pr + 0]);
        float s1 = __ldcg(&pp[NJ + 3 * pr + 1]);
        float s2 = __ldcg(&pp[NJ + 3 * pr + 2]);
        float t = sqrtf(s0) + sqrtf(s1) + sqrtf(s2);
        hem += t * t;
    }

    // l3d: 51 abs-diffs for batch tid
    float l = 0.f;
    const float* jb = joints + tid * NJ * 3;
    const float* pb = pred   + tid * NJ * 3;
    #pragma unroll
    for (int i = 0; i < NJ * 3; i++) l += fabsf(jb[i] - pb[i]);

    float v = l + 0.005f * (l2d + hem);
    __syncthreads();   // red[] reuse
    float tot = blockReduce256(v, red, tid);
    if (tid == 0) {
        out[0] = tot * (1.f / 256.f);
        g_count = 0;   // reset for next graph replay
    }
}

extern "C" void kernel_launch(void* const* d_in, const int* in_sizes, int n_in,
                              void* d_out, int out_size) {
    const float* pred   = (const float*)d_in[0];
    const float* joints = (const float*)d_in[1];
    const float* mo     = (const float*)d_in[2];
    const float* j2d    = (const float*)d_in[3];
    float* out = (float*)d_out;

    k_fused<<<dim3(NGRP, NB), 256>>>(mo, joints, j2d, pred, out);
}

// round 6
// speedup vs baseline: 1.1565x; 1.1435x over previous
#include <cuda_runtime.h>

#define NJ   17
#define NP   14
#define NB   256
#define NCH  59            // 17 + 3*14
#define GX   (NJ + NP)     // 31 block columns
#define NBLK (GX * NB)     // 7936 total blocks

__constant__ int c_par[NP] = {0,1,2,0,4,5,0,8,14,15,8,11,12,8};
__constant__ int c_chi[NP] = {1,2,3,4,5,6,8,14,15,16,11,12,13,10};

// Per-block partial results (every slot written every launch -> no pre-zeroing).
__device__ float        g_part[NBLK];
__device__ unsigned int g_count;   // zero at module load; last block resets each call

// max of exp(-(i-x)^2/4) over integer grid i in [0,63]: attained at nearest grid point.
__device__ __forceinline__ float gmax1d(float x) {
    float i = fminf(fmaxf(rintf(x), 0.f), 63.f);
    float d = i - x;
    return __expf(-d * d * 0.25f);
}

__device__ __forceinline__ float blockReduce256(float v, float* red, int tid) {
    #pragma unroll
    for (int o = 16; o > 0; o >>= 1) v += __shfl_down_sync(0xffffffffu, v, o);
    if ((tid & 31) == 0) red[tid >> 5] = v;
    __syncthreads();
    v = (tid < 8) ? red[tid] : 0.f;
    if (tid < 32) {
        #pragma unroll
        for (int o = 4; o > 0; o >>= 1) v += __shfl_down_sync(0xffffffffu, v, o);
    }
    return v;   // valid on tid 0
}

__global__ void __launch_bounds__(256, 8)
k_fused(const float* __restrict__ mo,
        const float* __restrict__ joints,
        const float* __restrict__ j2d,
        const float* __restrict__ pred,
        float* __restrict__ out) {
    __shared__ __align__(16) float ex[64], ey[64], ex2[64], ey2[64];
    __shared__ float red[8];
    __shared__ int   s_last;

    const int b    = blockIdx.y;
    const int tid  = threadIdx.x;
    const int lbid = b * GX + blockIdx.x;

    const float4* ey4  = (const float4*)ey;
    const float4* ey24 = (const float4*)ey2;

    float partial = 0.f;   // tid 0: this block's contribution to (L2D_sum + LHEM_sum)

    if (blockIdx.x < NJ) {
        // ---------------- L2D path ----------------
        const int j = blockIdx.x;
        const float x = j2d[(b * NJ + j) * 2 + 0] * 64.f;
        const float y = j2d[(b * NJ + j) * 2 + 1] * 64.f;
        const float inv = 1.f / (gmax1d(x) * gmax1d(y));
        if (tid < 64)       { float d = (float)tid - x;        ex[tid] = expf(-d * d * 0.25f) * inv; }
        else if (tid < 128) { int k = tid - 64; float d = (float)k - y; ey[k] = expf(-d * d * 0.25f); }
        __syncthreads();

        const float4* p = (const float4*)(mo + (((size_t)b * NCH + j) << 12));
        float acc = 0.f;
        #pragma unroll
        for (int it = 0; it < 4; it++) {
            int e4 = tid + it * 256;
            float4 m = p[e4];
            int i  = e4 >> 4;   // spatial row
            int k4 = e4 & 15;   // float4 column
            float  hx = ex[i];
            float4 v  = ey4[k4];
            float d0 = m.x - hx * v.x;
            float d1 = m.y - hx * v.y;
            float d2 = m.z - hx * v.z;
            float d3 = m.w - hx * v.w;
            acc += d0 * d0 + d1 * d1 + d2 * d2 + d3 * d3;
        }
        partial = blockReduce256(acc, red, tid);
    } else {
        // ---------------- HEM path ----------------
        const int pr = blockIdx.x - NJ;
        const int pj = c_par[pr], cj = c_chi[pr];
        const float xp = j2d[(b * NJ + pj) * 2 + 0] * 64.f;
        const float yp = j2d[(b * NJ + pj) * 2 + 1] * 64.f;
        const float xc = j2d[(b * NJ + cj) * 2 + 0] * 64.f;
        const float yc = j2d[(b * NJ + cj) * 2 + 1] * 64.f;
        const float invp = 1.f / (gmax1d(xp) * gmax1d(yp));
        const float invc = 1.f / (gmax1d(xc) * gmax1d(yc));
        if (tid < 64)       { float d = (float)tid - xp;         ex [tid] = expf(-d * d * 0.25f) * invp; }
        else if (tid < 128) { int k = tid - 64;  float d = (float)k - yp; ey [k] = expf(-d * d * 0.25f); }
        else if (tid < 192) { int k = tid - 128; float d = (float)k - xc; ex2[k] = expf(-d * d * 0.25f) * invc; }
        else                { int k = tid - 192; float d = (float)k - yc; ey2[k] = expf(-d * d * 0.25f); }
        __syncthreads();

        const float dz = joints[(b * NJ + pj) * 3 + 2] - joints[(b * NJ + cj) * 3 + 2];
        const int r = (dz > 0.1f) ? 1 : ((fabsf(dz) < 0.1f) ? 0 : -1);

        const float4* p0 = (const float4*)(mo + (((size_t)b * NCH + NJ + pr * 3) << 12));
        float a0 = 0.f, a1 = 0.f, a2 = 0.f;
        #pragma unroll
        for (int it = 0; it < 4; it++) {
            int e4 = tid + it * 256;
            int i  = e4 >> 4;
            int k4 = e4 & 15;
            float  hpx = ex[i];
            float  hcx = ex2[i];
            float4 vp  = ey4[k4];
            float4 vc  = ey24[k4];
            float m0[4], m1[4], m2[4];
            *(float4*)m0 = p0[e4];
            *(float4*)m1 = p0[e4 + 1024];
            *(float4*)m2 = p0[e4 + 2048];
            #pragma unroll
            for (int n = 0; n < 4; n++) {
                float hp = hpx * (&vp.x)[n];
                float hc = hcx * (&vc.x)[n];
                float t0 = (r == -1) ? hc : 0.f;
                float t1 = (r ==  0) ? (hp + hc) : hp;
                float t2 = (r ==  1) ? hc : 0.f;
                float d0 = t0 - m0[n];
                float d1 = t1 - m1[n];
                float d2 = t2 - m2[n];
                a0 += d0 * d0;
                a1 += d1 * d1;
                a2 += d2 * d2;
            }
        }
        float S0 = blockReduce256(a0, red, tid);
        __syncthreads();
        float S1 = blockReduce256(a1, red, tid);
        __syncthreads();
        float S2 = blockReduce256(a2, red, tid);
        if (tid == 0) {
            float s = sqrtf(S0) + sqrtf(S1) + sqrtf(S2);
            partial = s * s;
        }
    }

    // ---- publish partial, detect last block ----
    if (tid == 0) {
        g_part[lbid] = partial;
        __threadfence();
        unsigned int prev = atomicAdd(&g_count, 1u);
        s_last = (prev == (unsigned)(NBLK - 1)) ? 1 : 0;
    }
    __syncthreads();
    if (!s_last) return;

    // ---- last block: final reduction (float, positive terms) + l3d + output ----
    float s = 0.f;
    for (int i = tid; i < NBLK; i += 256) s += __ldcg(&g_part[i]);

    // l3d: thread tid handles batch tid (51 abs-diffs)
    float l = 0.f;
    const float* jb = joints + tid * NJ * 3;
    const float* pb = pred   + tid * NJ * 3;
    #pragma unroll
    for (int i = 0; i < NJ * 3; i++) l += fabsf(jb[i] - pb[i]);

    float v = l + 0.005f * s;
    __syncthreads();   // red[] reuse
    float tot = blockReduce256(v, red, tid);
    if (tid == 0) {
        out[0] = tot * (1.f / 256.f);
        g_count = 0;   // reset for next (graph-replayed) launch
    }
}

extern "C" void kernel_launch(void* const* d_in, const int* in_sizes, int n_in,
                              void* d_out, int out_size) {
    const float* pred   = (const float*)d_in[0];
    const float* joints = (const float*)d_in[1];
    const float* mo     = (const float*)d_in[2];
    const float* j2d    = (const float*)d_in[3];
    float* out = (float*)d_out;

    k_fused<<<dim3(GX, NB), 256>>>(mo, joints, j2d, pred, out);
}